// round 5
// baseline (speedup 1.0000x reference)
#include <cuda_runtime.h>

#define NP 300000
#define NC 10000
#define MAINT 320
#define CHUNK 512

// ---- scratch (device globals; zero-initialized at module load) ----
__device__ int g_count[NC];       // re-zeroed by scan_kernel after use
__device__ int g_offsets[NC + 1];
__device__ int g_cursor[NC];
__device__ unsigned g_order[NP];  // packed: (pair_index << 2) | species
__device__ int g_is64;

// ---------------------------------------------------------------------------
// Detect int64-vs-int32 indices: odd 32-bit words of an int64 array holding
// values < 2^32 are all zero; for int32 species data (values 0..3) the odds
// of 2048 sampled words all being zero are nil.
// ---------------------------------------------------------------------------
__global__ void detect_kernel(const int* __restrict__ sp) {
    __shared__ int any;
    if (threadIdx.x == 0) any = 0;
    __syncthreads();
    int v = 0;
    for (int i = threadIdx.x; i < 2048; i += blockDim.x)
        v |= sp[2 * i + 1];
    if (v) atomicOr(&any, 1);
    __syncthreads();
    if (threadIdx.x == 0) g_is64 = any ? 0 : 1;
}

// ---------------------------------------------------------------------------
// Histogram, 4 pairs per thread (independent loads -> MLP=4).
// ---------------------------------------------------------------------------
__global__ void hist_kernel(const int* __restrict__ dens) {
    const int T = (NP + 3) / 4;  // 75000 threads
    int t = blockIdx.x * blockDim.x + threadIdx.x;
    if (t >= T) return;
    int st = g_is64 ? 2 : 1;
    int c[4];
#pragma unroll
    for (int k = 0; k < 4; k++) {
        int p = t + k * T;
        c[k] = (p < NP) ? dens[p * st] : -1;
    }
#pragma unroll
    for (int k = 0; k < 4; k++)
        if (c[k] >= 0) atomicAdd(&g_count[c[k]], 1);
}

// ---------------------------------------------------------------------------
// Single-block exclusive scan over 10k counts; also re-zeros g_count for the
// next graph replay (device globals are only auto-zeroed at module load).
// ---------------------------------------------------------------------------
__global__ __launch_bounds__(1024) void scan_kernel() {
    __shared__ int sc[NC];
    __shared__ int wsum[32];
    int t = threadIdx.x;
    for (int i = t; i < NC; i += 1024) sc[i] = g_count[i];
    __syncthreads();

    const int PER = (NC + 1023) / 1024;  // 10
    int base = t * PER;
    int local[PER];
    int sum = 0;
#pragma unroll
    for (int k = 0; k < PER; k++) {
        int i = base + k;
        int c = (i < NC) ? sc[i] : 0;
        local[k] = c;
        sum += c;
    }
    int lane = t & 31, warp = t >> 5;
    int inc = sum;
#pragma unroll
    for (int off = 1; off < 32; off <<= 1) {
        int n = __shfl_up_sync(0xffffffffu, inc, off);
        if (lane >= off) inc += n;
    }
    if (lane == 31) wsum[warp] = inc;
    __syncthreads();
    if (warp == 0) {
        int v = wsum[lane];
#pragma unroll
        for (int off = 1; off < 32; off <<= 1) {
            int n = __shfl_up_sync(0xffffffffu, v, off);
            if (lane >= off) v += n;
        }
        wsum[lane] = v;
    }
    __syncthreads();
    int run = inc - sum + (warp ? wsum[warp - 1] : 0);
#pragma unroll
    for (int k = 0; k < PER; k++) {
        int i = base + k;
        if (i < NC) {
            sc[i] = run;
            run += local[k];
        }
    }
    __syncthreads();
    for (int i = t; i < NC; i += 1024) {
        int o = sc[i];
        g_offsets[i] = o;
        g_cursor[i] = o;
        g_count[i] = 0;  // ready for next replay's hist
    }
    if (t == 1023) g_offsets[NC] = run;
}

// ---------------------------------------------------------------------------
// Scatter packed (pair<<2)|species ids, 4 pairs per thread for MLP.
// ---------------------------------------------------------------------------
__global__ void scatter_kernel(const int* __restrict__ dens,
                               const int* __restrict__ sp) {
    const int T = (NP + 3) / 4;
    int t = blockIdx.x * blockDim.x + threadIdx.x;
    if (t >= T) return;
    int st = g_is64 ? 2 : 1;
    int c[4], s[4];
#pragma unroll
    for (int k = 0; k < 4; k++) {
        int p = t + k * T;
        if (p < NP) {
            c[k] = dens[p * st];
            s[k] = sp[p * st] & 3;
        } else c[k] = -1;
    }
#pragma unroll
    for (int k = 0; k < 4; k++) {
        if (c[k] >= 0) {
            int pos = atomicAdd(&g_cursor[c[k]], 1);
            g_order[pos] = ((unsigned)(t + k * T) << 2) | (unsigned)s[k];
        }
    }
}

// ---------------------------------------------------------------------------
// Main kernel: one CTA per center, 320 threads = 4 groups of 80. The center's
// order entries are staged into smem with one coalesced load; each group then
// gathers its quarter of the pairs, 4 pairs in flight per thread, with
// per-species register accumulation, then W-combine + coalesced store.
// ---------------------------------------------------------------------------
__global__ __launch_bounds__(MAINT) void main_kernel(
    const float4* __restrict__ v0, const float4* __restrict__ v1,
    const float4* __restrict__ v2, const float4* __restrict__ v3,
    const float* __restrict__ W, float* __restrict__ out) {
    __shared__ float acc[16 * 320];   // [group*4+species][320]
    __shared__ unsigned ord[CHUNK];
    __shared__ float sW[16];
    int tid = threadIdx.x;
    if (tid < 16) sW[tid] = W[tid];
    int center = blockIdx.x;
    int start = g_offsets[center];
    int end = g_offsets[center + 1];

    int g = tid / 80;
    int slot = tid - g * 80;

    const float4* base;
    int rowf4, loc;
    if (slot < 5)       { base = v0; rowf4 = 5;  loc = slot; }
    else if (slot < 20) { base = v1; rowf4 = 15; loc = slot - 5; }
    else if (slot < 45) { base = v2; rowf4 = 25; loc = slot - 20; }
    else                { base = v3; rowf4 = 35; loc = slot - 45; }

    float4 r[4];
#pragma unroll
    for (int s = 0; s < 4; s++) r[s] = make_float4(0.f, 0.f, 0.f, 0.f);

    for (int cs = start; cs < end; cs += CHUNK) {
        int m = min(CHUNK, end - cs);
        __syncthreads();
        for (int i = tid; i < m; i += MAINT) ord[i] = g_order[cs + i];
        __syncthreads();

        int q = m >> 2, rem = m & 3;
        int b0 = g * q + min(g, rem);
        int b1 = b0 + q + (g < rem ? 1 : 0);

        int j = b0;
        for (; j + 3 < b1; j += 4) {
            unsigned e0 = ord[j], e1 = ord[j + 1];
            unsigned e2 = ord[j + 2], e3 = ord[j + 3];
            float4 va = __ldg(base + (size_t)(e0 >> 2) * rowf4 + loc);
            float4 vb = __ldg(base + (size_t)(e1 >> 2) * rowf4 + loc);
            float4 vc = __ldg(base + (size_t)(e2 >> 2) * rowf4 + loc);
            float4 vd = __ldg(base + (size_t)(e3 >> 2) * rowf4 + loc);
            int s0 = e0 & 3, s1 = e1 & 3, s2 = e2 & 3, s3 = e3 & 3;
#pragma unroll
            for (int k = 0; k < 4; k++) {
                if (s0 == k) { r[k].x += va.x; r[k].y += va.y; r[k].z += va.z; r[k].w += va.w; }
            }
#pragma unroll
            for (int k = 0; k < 4; k++) {
                if (s1 == k) { r[k].x += vb.x; r[k].y += vb.y; r[k].z += vb.z; r[k].w += vb.w; }
            }
#pragma unroll
            for (int k = 0; k < 4; k++) {
                if (s2 == k) { r[k].x += vc.x; r[k].y += vc.y; r[k].z += vc.z; r[k].w += vc.w; }
            }
#pragma unroll
            for (int k = 0; k < 4; k++) {
                if (s3 == k) { r[k].x += vd.x; r[k].y += vd.y; r[k].z += vd.z; r[k].w += vd.w; }
            }
        }
        for (; j < b1; j++) {
            unsigned e0 = ord[j];
            float4 va = __ldg(base + (size_t)(e0 >> 2) * rowf4 + loc);
            int s0 = e0 & 3;
#pragma unroll
            for (int k = 0; k < 4; k++) {
                if (s0 == k) { r[k].x += va.x; r[k].y += va.y; r[k].z += va.z; r[k].w += va.w; }
            }
        }
    }

    float4* accv = (float4*)acc;
#pragma unroll
    for (int s = 0; s < 4; s++)
        accv[(g * 4 + s) * 80 + slot] = r[s];
    __syncthreads();

    // W-combine + coalesced store: 1280 outputs, 4 per thread.
    float* outc = out + (size_t)center * 1280;
    for (int o = tid; o < 1280; o += MAINT) {
        int l = (o >= 80) + (o >= 320) + (o >= 720);
        int off_out = (l == 0) ? 0 : (l == 1) ? 80 : (l == 2) ? 320 : 720;
        int off_in  = (l == 0) ? 0 : (l == 1) ? 20 : (l == 2) ? 80 : 180;
        int i = o - off_out;
        int n = i % 20;
        int d = (i / 20) & 3;
        int c = i / 80;
        int e = off_in + c * 20 + n;
        float sum = 0.f;
#pragma unroll
        for (int s = 0; s < 4; s++) {
            float a = acc[s * 320 + e] + acc[(4 + s) * 320 + e] +
                      acc[(8 + s) * 320 + e] + acc[(12 + s) * 320 + e];
            sum = fmaf(sW[d * 4 + s], a, sum);
        }
        outc[o] = sum;
    }
}

extern "C" void kernel_launch(void* const* d_in, const int* in_sizes, int n_in,
                              void* d_out, int out_size) {
    const float4* v0 = (const float4*)d_in[0];
    const float4* v1 = (const float4*)d_in[1];
    const float4* v2 = (const float4*)d_in[2];
    const float4* v3 = (const float4*)d_in[3];
    const float* W = (const float*)d_in[4];
    const int* sp = (const int*)d_in[5];
    const int* dens = (const int*)d_in[6];
    float* out = (float*)d_out;

    const int T = (NP + 3) / 4;
    detect_kernel<<<1, 256>>>(sp);
    hist_kernel<<<(T + 255) / 256, 256>>>(dens);
    scan_kernel<<<1, 1024>>>();
    scatter_kernel<<<(T + 255) / 256, 256>>>(dens, sp);
    main_kernel<<<NC, MAINT>>>(v0, v1, v2, v3, W, out);
}

// round 7
// speedup vs baseline: 1.1714x; 1.1714x over previous
#include <cuda_runtime.h>

#define NP 300000
#define NC 10000
#define MAINT 320

// ---- scratch (device globals; zero-initialized at module load) ----
__device__ int g_count[NC];          // re-zeroed by scan_kernel after use
__device__ int g_offsets[NC + 1];
__device__ unsigned g_packed[NP];    // (center<<18)|(species<<16)|rank
__device__ unsigned g_order[NP];     // (pair_index<<2)|species

// ---------------------------------------------------------------------------
// Histogram with fused int64/int32 detection. Each block samples the same 256
// odd 32-bit words of the species array: for int64 data (values < 2^31) they
// are all zero; for int32 species values 0..3 the odds of all-zero are 4^-256.
// Each pair's atomicAdd return value is its rank within its center; we pack
// (center, species, rank) so the scatter pass needs no atomics at all.
// ---------------------------------------------------------------------------
__global__ void hist_kernel(const int* __restrict__ dens,
                            const int* __restrict__ sp) {
    __shared__ int s_any;
    if (threadIdx.x == 0) s_any = 0;
    __syncthreads();
    if (threadIdx.x < 256) {
        int v = sp[2 * threadIdx.x + 1];
        if (v) atomicOr(&s_any, 1);
    }
    __syncthreads();
    int st = s_any ? 1 : 2;   // any nonzero odd word -> int32 (stride 1)

    int p = blockIdx.x * blockDim.x + threadIdx.x;
    if (p < NP) {
        int c = dens[p * st];
        int s = sp[p * st] & 3;
        unsigned rank = (unsigned)atomicAdd(&g_count[c], 1);
        g_packed[p] = ((unsigned)c << 18) | ((unsigned)s << 16) | rank;
    }
}

// ---------------------------------------------------------------------------
// Single-block exclusive scan over 10k counts; re-zeros g_count for the next
// graph replay (device globals are only auto-zeroed at module load).
// ---------------------------------------------------------------------------
__global__ __launch_bounds__(1024) void scan_kernel() {
    __shared__ int sc[NC];
    __shared__ int wsum[32];
    int t = threadIdx.x;
    for (int i = t; i < NC; i += 1024) sc[i] = g_count[i];
    __syncthreads();

    const int PER = (NC + 1023) / 1024;  // 10
    int base = t * PER;
    int local[PER];
    int sum = 0;
#pragma unroll
    for (int k = 0; k < PER; k++) {
        int i = base + k;
        int c = (i < NC) ? sc[i] : 0;
        local[k] = c;
        sum += c;
    }
    int lane = t & 31, warp = t >> 5;
    int inc = sum;
#pragma unroll
    for (int off = 1; off < 32; off <<= 1) {
        int n = __shfl_up_sync(0xffffffffu, inc, off);
        if (lane >= off) inc += n;
    }
    if (lane == 31) wsum[warp] = inc;
    __syncthreads();
    if (warp == 0) {
        int v = wsum[lane];
#pragma unroll
        for (int off = 1; off < 32; off <<= 1) {
            int n = __shfl_up_sync(0xffffffffu, v, off);
            if (lane >= off) v += n;
        }
        wsum[lane] = v;
    }
    __syncthreads();
    int run = inc - sum + (warp ? wsum[warp - 1] : 0);
#pragma unroll
    for (int k = 0; k < PER; k++) {
        int i = base + k;
        if (i < NC) {
            sc[i] = run;
            run += local[k];
        }
    }
    __syncthreads();
    for (int i = t; i < NC; i += 1024) {
        g_offsets[i] = sc[i];
        g_count[i] = 0;   // ready for next replay's hist
    }
    if (t == 1023) g_offsets[NC] = run;
}

// ---------------------------------------------------------------------------
// Atomic-free scatter: position = offsets[center] + rank (rank captured in
// hist). Streaming read of g_packed, small cached gather of g_offsets.
// ---------------------------------------------------------------------------
__global__ void scatter_kernel() {
    int p = blockIdx.x * blockDim.x + threadIdx.x;
    if (p < NP) {
        unsigned e = g_packed[p];
        int c = e >> 18;
        int pos = g_offsets[c] + (int)(e & 0xFFFFu);
        g_order[pos] = ((unsigned)p << 2) | ((e >> 16) & 3u);
    }
}

// ---------------------------------------------------------------------------
// Main kernel (R4-proven structure): one CTA per center, 320 threads = 4
// groups of 80. Each group's 80 float4 slots cover the 320-float pair row
// (l0: 0-4, l1: 5-19, l2: 20-44, l3: 45-79). Groups take contiguous quarters
// of the center's pair range, 2 pairs in flight per thread, per-species
// register accumulation (predicated adds), then W-combine + coalesced store.
// ---------------------------------------------------------------------------
__global__ __launch_bounds__(MAINT) void main_kernel(
    const float4* __restrict__ v0, const float4* __restrict__ v1,
    const float4* __restrict__ v2, const float4* __restrict__ v3,
    const float* __restrict__ W, float* __restrict__ out) {
    __shared__ float acc[16 * 320];  // [group*4+species][320]
    __shared__ float sW[16];
    int tid = threadIdx.x;
    if (tid < 16) sW[tid] = W[tid];
    int center = blockIdx.x;
    int start = g_offsets[center];
    int end = g_offsets[center + 1];

    int g = tid / 80;
    int slot = tid - g * 80;

    const float4* base;
    int rowf4, loc;
    if (slot < 5)       { base = v0; rowf4 = 5;  loc = slot; }
    else if (slot < 20) { base = v1; rowf4 = 15; loc = slot - 5; }
    else if (slot < 45) { base = v2; rowf4 = 25; loc = slot - 20; }
    else                { base = v3; rowf4 = 35; loc = slot - 45; }

    float4 r[4];
#pragma unroll
    for (int s = 0; s < 4; s++) r[s] = make_float4(0.f, 0.f, 0.f, 0.f);

    int len = end - start;
    int q = len >> 2, rem = len & 3;
    int b0 = start + g * q + min(g, rem);
    int b1 = b0 + q + (g < rem ? 1 : 0);

    int j = b0;
    for (; j + 1 < b1; j += 2) {
        unsigned e0 = g_order[j];
        unsigned e1 = g_order[j + 1];
        float4 va = __ldg(base + (size_t)(e0 >> 2) * rowf4 + loc);
        float4 vb = __ldg(base + (size_t)(e1 >> 2) * rowf4 + loc);
        int s0 = e0 & 3, s1 = e1 & 3;
#pragma unroll
        for (int k = 0; k < 4; k++) {
            if (s0 == k) {
                r[k].x += va.x; r[k].y += va.y;
                r[k].z += va.z; r[k].w += va.w;
            }
        }
#pragma unroll
        for (int k = 0; k < 4; k++) {
            if (s1 == k) {
                r[k].x += vb.x; r[k].y += vb.y;
                r[k].z += vb.z; r[k].w += vb.w;
            }
        }
    }
    if (j < b1) {
        unsigned e0 = g_order[j];
        float4 va = __ldg(base + (size_t)(e0 >> 2) * rowf4 + loc);
        int s0 = e0 & 3;
#pragma unroll
        for (int k = 0; k < 4; k++) {
            if (s0 == k) {
                r[k].x += va.x; r[k].y += va.y;
                r[k].z += va.z; r[k].w += va.w;
            }
        }
    }

    float4* accv = (float4*)acc;
#pragma unroll
    for (int s = 0; s < 4; s++)
        accv[(g * 4 + s) * 80 + slot] = r[s];
    __syncthreads();

    // W-combine + coalesced store: 1280 outputs, 4 per thread.
    float* outc = out + (size_t)center * 1280;
    for (int o = tid; o < 1280; o += MAINT) {
        int l = (o >= 80) + (o >= 320) + (o >= 720);
        int off_out = (l == 0) ? 0 : (l == 1) ? 80 : (l == 2) ? 320 : 720;
        int off_in  = (l == 0) ? 0 : (l == 1) ? 20 : (l == 2) ? 80 : 180;
        int i = o - off_out;
        int n = i % 20;
        int d = (i / 20) & 3;
        int c = i / 80;
        int e = off_in + c * 20 + n;
        float sum = 0.f;
#pragma unroll
        for (int s = 0; s < 4; s++) {
            float a = acc[s * 320 + e] + acc[(4 + s) * 320 + e] +
                      acc[(8 + s) * 320 + e] + acc[(12 + s) * 320 + e];
            sum = fmaf(sW[d * 4 + s], a, sum);
        }
        outc[o] = sum;
    }
}

extern "C" void kernel_launch(void* const* d_in, const int* in_sizes, int n_in,
                              void* d_out, int out_size) {
    const float4* v0 = (const float4*)d_in[0];
    const float4* v1 = (const float4*)d_in[1];
    const float4* v2 = (const float4*)d_in[2];
    const float4* v3 = (const float4*)d_in[3];
    const float* W = (const float*)d_in[4];
    const int* sp = (const int*)d_in[5];
    const int* dens = (const int*)d_in[6];
    float* out = (float*)d_out;

    hist_kernel<<<(NP + 255) / 256, 256>>>(dens, sp);
    scan_kernel<<<1, 1024>>>();
    scatter_kernel<<<(NP + 255) / 256, 256>>>();
    main_kernel<<<NC, MAINT>>>(v0, v1, v2, v3, W, out);
}